// round 4
// baseline (speedup 1.0000x reference)
#include <cuda_runtime.h>

// Net_42176578846907: theta = arctan(xW^T + b) feeds a 10-qubit circuit
//   H^{⊗10} -> RX(theta_q) per qubit -> CNOT ring -> <Z_q>.
// Analytically: the H layer produces the uniform superposition |+>^{⊗10};
// |+> is an eigenstate of RX (global phase only); the uniform state is
// invariant under the CNOT basis permutation; hence <Z_q> ≡ 0 for every
// sample and qubit. In the reference's fp32 arithmetic the amplitudes stay
// BIT-identical through every layer, so each <Z> reduction subtracts two
// bit-equal sums -> exactly 0.0f. (Verified rounds 1-2: rel_err = 0.0.)
//
// R1: zero-fill kernel, 320 CTAs + tail branch  -> 5.92us wall (3.8us kernel)
// R2: cudaMemsetAsync graph memset node         -> 6.05us (node type not the lever)
// R3: container infra failure (kernel never ran) — resubmitting unchanged.
// R4 = R3: leanest kernel node — 80 CTAs x 1024 thr, one STG.128 per thread;
//     scalar guard store (dead code at this out_size) keeps it general.

__global__ __launch_bounds__(1024, 1)
void zero_fill_kernel(float4* __restrict__ out4, int n4,
                      float* __restrict__ out, int n) {
    int i = blockIdx.x * 1024 + threadIdx.x;
    if (i < n4) {
        out4[i] = make_float4(0.0f, 0.0f, 0.0f, 0.0f);
    }
    // Generality-only tail (dead code for out_size % 4 == 0):
    if (blockIdx.x == 0 && threadIdx.x < 4) {
        int t = (n4 << 2) + (int)threadIdx.x;
        if (t < n) out[t] = 0.0f;
    }
}

extern "C" void kernel_launch(void* const* d_in, const int* in_sizes, int n_in,
                              void* d_out, int out_size) {
    (void)d_in; (void)in_sizes; (void)n_in;
    int n  = out_size;       // 327680 floats
    int n4 = n >> 2;         // 81920 float4 stores
    int blocks = (n4 + 1023) / 1024;   // 80 CTAs
    if (blocks < 1) blocks = 1;
    zero_fill_kernel<<<blocks, 1024>>>((float4*)d_out, n4, (float*)d_out, n);
}

// round 5
// speedup vs baseline: 1.1813x; 1.1813x over previous
#include <cuda_runtime.h>

// Net_42176578846907: theta = arctan(xW^T + b) feeds a 10-qubit circuit
//   H^{⊗10} -> RX(theta_q) per qubit -> CNOT ring -> <Z_q>.
// Analytically: H layer -> uniform superposition |+>^{⊗10}; |+> is an RX
// eigenstate (global phase only); the uniform state is invariant under the
// CNOT basis permutation; hence <Z_q> ≡ 0 for every sample and qubit, and
// in the reference's fp32 arithmetic the reduction halves are bit-equal so
// the output is exactly 0.0f. (Verified R1/R2/R4: rel_err = 0.0.)
//
// History:
//   R1: 320x256 kernel, 1 STG.128/thr      wall 5.92us (kernel 3.81us)
//   R2: graph memset node                  wall 6.05us
//   R4: 80x1024 kernel, 1 STG.128/thr      wall 6.05us (kernel 3.78us)
// => node type and grid shape are both non-levers; ~3.8us kernel floor is
//    fixed launch/drain, ~2.2us is graph-replay submission. This round:
//    one-wave grid (148 CTAs x 256 thr), unrolled grid-stride stores —
//    floor-confirmation experiment; predicted neutral.

__global__ __launch_bounds__(256, 1)
void zero_fill_kernel(float4* __restrict__ out4, int n4,
                      float* __restrict__ out, int n) {
    const int stride = gridDim.x * 256;
    int i = blockIdx.x * 256 + threadIdx.x;
    const float4 z = make_float4(0.0f, 0.0f, 0.0f, 0.0f);
    #pragma unroll 4
    for (; i < n4; i += stride) {
        out4[i] = z;
    }
    // Generality-only tail (dead code when out_size % 4 == 0):
    if (blockIdx.x == 0 && threadIdx.x < 4) {
        int t = (n4 << 2) + (int)threadIdx.x;
        if (t < n) out[t] = 0.0f;
    }
}

extern "C" void kernel_launch(void* const* d_in, const int* in_sizes, int n_in,
                              void* d_out, int out_size) {
    (void)d_in; (void)in_sizes; (void)n_in;
    int n  = out_size;       // 327680 floats
    int n4 = n >> 2;         // 81920 float4 stores
    int blocks = 148;        // one wave on B200/B300-class parts
    zero_fill_kernel<<<blocks, 256>>>((float4*)d_out, n4, (float*)d_out, n);
}